// round 12
// baseline (speedup 1.0000x reference)
#include <cuda_runtime.h>
#include <cuda_fp16.h>

// ---------------------------------------------------------------------------
// Net_16673063043559: 2-layer dense GCN on GB300 (sm_103a, baseline-PTX only)
//   degconv: row/col sums of m + fp16 conversion (one streaming pass over m)
//   L1:  msg = relu(emb[x] @ w1^T + b1)*csc ; h = rs*(m @ msg)  [split-K=4]
//   L2:  msg = relu((sum g_h0..3) @ w2^T + b2)*csc ; h = rs*(m @ msg)
//   pool: 2-stage segment max (atomicMax on float bits; h >= 0), classify
// Propagate GEMM: fp16 HMMA m16n8k16, CTA tile 128x128, warp tile 32x64,
// cp.async 3-stage ring. (At the legacy mma.sync rate ceiling.)
// Linear: single-barrier, whole-w staged in smem, float4 weight LDS.
// ---------------------------------------------------------------------------

#define NN     8192
#define FDIM   128
#define NGRAPH 64
#define NCLS   16

// GEMM tiling
#define BM     128
#define BK     32
#define APAD   40     // halves per A smem row (80B stride)
#define BPAD   136    // halves per B smem row (272B stride)
#define NSTAGE 3
#define KSPLIT 4
#define KQ     (NN / KSPLIT)      // 2048
#define KTILES (KQ / BK)          // 64

#define ABYTES (BM * APAD * 2)    // 10240
#define BBYTES (BK * BPAD * 2)    // 8704
#define SMEM_GEMM (NSTAGE * (ABYTES + BBYTES))   // 56832

// Linear smem: ht 32x132 + wt 128x132 floats
#define LIN_HT_ELEMS (32 * 132)
#define LIN_WT_ELEMS (128 * 132)
#define SMEM_LIN ((LIN_HT_ELEMS + LIN_WT_ELEMS) * 4)   // 84480

// Scratch (device globals: no allocation allowed)
__device__ __half g_mh[(size_t)NN * NN];   // fp16 copy of m (128 MB)
__device__ __half g_msg[NN * FDIM];        // scaled message (fp16, GEMM B)
__device__ float  g_h0[NN * FDIM];         // split-K partials (rs-scaled)
__device__ float  g_h1[NN * FDIM];
__device__ float  g_h2[NN * FDIM];
__device__ float  g_h3[NN * FDIM];
__device__ float  g_rowdeg[NN];
__device__ float  g_coldeg[NN];
__device__ unsigned g_poolbits[NGRAPH * FDIM];   // float bits (values >= 0)

// ---------------------------------------------------------------------------
__device__ __forceinline__ unsigned smem_u32(const void* p) {
    return (unsigned)__cvta_generic_to_shared(p);
}
__device__ __forceinline__ void cp_async16(unsigned s, const void* g) {
    asm volatile("cp.async.cg.shared.global [%0], [%1], 16;\n" :: "r"(s), "l"(g));
}
__device__ __forceinline__ void cp_commit() {
    asm volatile("cp.async.commit_group;\n");
}
template <int N>
__device__ __forceinline__ void cp_wait() {
    asm volatile("cp.async.wait_group %0;\n" :: "n"(N));
}
__device__ __forceinline__ void ldsm4(unsigned r[4], unsigned a) {
    asm volatile("ldmatrix.sync.aligned.m8n8.x4.shared.b16 {%0,%1,%2,%3}, [%4];"
                 : "=r"(r[0]), "=r"(r[1]), "=r"(r[2]), "=r"(r[3]) : "r"(a));
}
__device__ __forceinline__ void ldsm4t(unsigned r[4], unsigned a) {
    asm volatile("ldmatrix.sync.aligned.m8n8.x4.trans.shared.b16 {%0,%1,%2,%3}, [%4];"
                 : "=r"(r[0]), "=r"(r[1]), "=r"(r[2]), "=r"(r[3]) : "r"(a));
}
__device__ __forceinline__ void mma_f16(float c[4], const unsigned a[4],
                                        unsigned b0, unsigned b1) {
    asm volatile(
        "mma.sync.aligned.m16n8k16.row.col.f32.f16.f16.f32 "
        "{%0,%1,%2,%3}, {%4,%5,%6,%7}, {%8,%9}, {%0,%1,%2,%3};"
        : "+f"(c[0]), "+f"(c[1]), "+f"(c[2]), "+f"(c[3])
        : "r"(a[0]), "r"(a[1]), "r"(a[2]), "r"(a[3]), "r"(b0), "r"(b1));
}

// ---------------------------------------------------------------------------
// Zero accumulators each replay (atomics accumulate; graph determinism).
__global__ void zero_deg_kernel() {
    int i = blockIdx.x * blockDim.x + threadIdx.x;
    if (i < NN) { g_rowdeg[i] = 0.f; g_coldeg[i] = 0.f; }
    if (i < NGRAPH * FDIM) g_poolbits[i] = 0u;   // valid: pooled values >= 0
}

// ---------------------------------------------------------------------------
// One streaming pass over m: row sums, col sums, fp16 conversion.
// Thread owns 4 consecutive columns. Grid (8, 128) -> 1024 CTAs.
__global__ __launch_bounds__(256) void degconv_kernel(const float* __restrict__ m) {
    const int c    = (blockIdx.x * 256 + threadIdx.x) * 4;
    const int r0   = blockIdx.y * 64;
    const int lane = threadIdx.x & 31;
    float ca0 = 0.f, ca1 = 0.f, ca2 = 0.f, ca3 = 0.f;

    for (int r = r0; r < r0 + 64; r += 8) {
        float4 v[8];
        float  rs[8];
#pragma unroll
        for (int j = 0; j < 8; j++)
            v[j] = __ldcs((const float4*)&m[(size_t)(r + j) * NN + c]);
#pragma unroll
        for (int j = 0; j < 8; j++) {
            __half2 h01 = __floats2half2_rn(v[j].x, v[j].y);
            __half2 h23 = __floats2half2_rn(v[j].z, v[j].w);
            uint2 pk = make_uint2(*(unsigned*)&h01, *(unsigned*)&h23);
            __stcs((uint2*)&g_mh[(size_t)(r + j) * NN + c], pk);
            ca0 += v[j].x; ca1 += v[j].y; ca2 += v[j].z; ca3 += v[j].w;
            rs[j] = (v[j].x + v[j].y) + (v[j].z + v[j].w);
        }
#pragma unroll
        for (int j = 0; j < 8; j++) {
            rs[j] += __shfl_xor_sync(0xffffffffu, rs[j], 16);
            rs[j] += __shfl_xor_sync(0xffffffffu, rs[j], 8);
            rs[j] += __shfl_xor_sync(0xffffffffu, rs[j], 4);
            rs[j] += __shfl_xor_sync(0xffffffffu, rs[j], 2);
            rs[j] += __shfl_xor_sync(0xffffffffu, rs[j], 1);
        }
        if (lane == 0) {
#pragma unroll
            for (int j = 0; j < 8; j++)
                atomicAdd(&g_rowdeg[r + j], rs[j]);
        }
    }
    atomicAdd(&g_coldeg[c + 0], ca0);
    atomicAdd(&g_coldeg[c + 1], ca1);
    atomicAdd(&g_coldeg[c + 2], ca2);
    atomicAdd(&g_coldeg[c + 3], ca3);
}

// ---------------------------------------------------------------------------
// g_msg = relu(in @ w^T + b) * rsqrt(col_deg[row]) as fp16.
// in = gather(emb, x) (gather=1) or g_h0+g_h1+g_h2+g_h3 (gather=0).
// Whole-w staged once (single barrier); thread owns 4 nodes x 4 consecutive
// cols; weight reads are one float4 LDS per k.
__global__ __launch_bounds__(256) void linear_kernel(
    const float* __restrict__ ext, const int* __restrict__ idx,
    const float* __restrict__ w, const float* __restrict__ b, int gather) {
    extern __shared__ float lsm[];
    float* ht = lsm;                    // [node][k], stride 132
    float* wt = lsm + LIN_HT_ELEMS;     // [k][c],    stride 132

    const int tid  = threadIdx.x;
    const int brow = blockIdx.x * 32;
    const int rg   = tid >> 5;          // warp -> 4 nodes
    const int cg   = tid & 31;          // lane -> 4 consecutive cols

    // stage input rows: thread -> node (tid>>3), 16 floats at (tid&7)*16
    {
        const int sr = tid >> 3;
        const int f0 = (tid & 7) * 16;
        const int node = brow + sr;
        if (gather) {
            const float* src = ext + (size_t)idx[node] * FDIM + f0;
#pragma unroll
            for (int q = 0; q < 4; q++) {
                float4 v = *(const float4*)(src + q * 4);
                ht[sr * 132 + f0 + q * 4 + 0] = v.x;
                ht[sr * 132 + f0 + q * 4 + 1] = v.y;
                ht[sr * 132 + f0 + q * 4 + 2] = v.z;
                ht[sr * 132 + f0 + q * 4 + 3] = v.w;
            }
        } else {
            const size_t o = (size_t)node * FDIM + f0;
#pragma unroll
            for (int q = 0; q < 4; q++) {
                float4 a0 = *(const float4*)&g_h0[o + q * 4];
                float4 a1 = *(const float4*)&g_h1[o + q * 4];
                float4 a2 = *(const float4*)&g_h2[o + q * 4];
                float4 a3 = *(const float4*)&g_h3[o + q * 4];
                ht[sr * 132 + f0 + q * 4 + 0] = (a0.x + a1.x) + (a2.x + a3.x);
                ht[sr * 132 + f0 + q * 4 + 1] = (a0.y + a1.y) + (a2.y + a3.y);
                ht[sr * 132 + f0 + q * 4 + 2] = (a0.z + a1.z) + (a2.z + a3.z);
                ht[sr * 132 + f0 + q * 4 + 3] = (a0.w + a1.w) + (a2.w + a3.w);
            }
        }
    }

    // stage whole w transposed: wt[k][c] = w[c][k]; 4096 float4, 16/thread
#pragma unroll
    for (int i = 0; i < 16; i++) {
        int id = tid + i * 256;          // 0..4095
        int c  = id >> 5;                // 0..127
        int k4 = (id & 31) * 4;          // 0..124
        float4 v = *(const float4*)&w[(size_t)c * FDIM + k4];
        wt[(k4 + 0) * 132 + c] = v.x;
        wt[(k4 + 1) * 132 + c] = v.y;
        wt[(k4 + 2) * 132 + c] = v.z;
        wt[(k4 + 3) * 132 + c] = v.w;
    }
    __syncthreads();

    float acc[4][4];
#pragma unroll
    for (int j = 0; j < 4; j++)
#pragma unroll
        for (int jj = 0; jj < 4; jj++) acc[j][jj] = 0.f;

#pragma unroll 4
    for (int k = 0; k < FDIM; k++) {
        float4 wv = *(const float4*)&wt[k * 132 + cg * 4];
        float hvv[4];
#pragma unroll
        for (int j = 0; j < 4; j++) hvv[j] = ht[(rg * 4 + j) * 132 + k];
#pragma unroll
        for (int j = 0; j < 4; j++) {
            acc[j][0] += hvv[j] * wv.x;
            acc[j][1] += hvv[j] * wv.y;
            acc[j][2] += hvv[j] * wv.z;
            acc[j][3] += hvv[j] * wv.w;
        }
    }

    const float4 bv = *(const float4*)&b[cg * 4];
#pragma unroll
    for (int j = 0; j < 4; j++) {
        const int rr = brow + rg * 4 + j;
        const float sc = rsqrtf(g_coldeg[rr]);
        float v0 = fmaxf(acc[j][0] + bv.x, 0.f) * sc;
        float v1 = fmaxf(acc[j][1] + bv.y, 0.f) * sc;
        float v2 = fmaxf(acc[j][2] + bv.z, 0.f) * sc;
        float v3 = fmaxf(acc[j][3] + bv.w, 0.f) * sc;
        __half2 h01 = __floats2half2_rn(v0, v1);
        __half2 h23 = __floats2half2_rn(v2, v3);
        *(uint2*)&g_msg[(size_t)rr * FDIM + cg * 4] =
            make_uint2(*(unsigned*)&h01, *(unsigned*)&h23);
    }
}

// ---------------------------------------------------------------------------
// Split-K propagate GEMM: partial = rs * (g_mh[:, Ks] @ g_msg[Ks, :]).
// Grid (64, 4): x = M tile (128 rows), y = K quarter. 256 CTAs, 2/SM.
// 8 warps: 4 along m (32 rows each) x 2 along n (64 cols each).
__global__ void __launch_bounds__(256, 2) gemm_fp16_kernel() {
    extern __shared__ __half smem[];
    const unsigned sb  = smem_u32(smem);              // A stages base
    const unsigned sbB = sb + NSTAGE * ABYTES;        // B stages base

    const int tid  = threadIdx.x;
    const int brow = blockIdx.x * BM;
    const int koff = blockIdx.y * KQ;
    float* out = (blockIdx.y == 0) ? g_h0 :
                 (blockIdx.y == 1) ? g_h1 :
                 (blockIdx.y == 2) ? g_h2 : g_h3;

    const int warp = tid >> 5, lane = tid & 31;
    const int wm   = (warp & 3) * 32;     // 0,32,64,96
    const int wn   = (warp >> 2) * 64;    // 0,64

    // A staging: 128 rows x 4 chunks of 16B = 512 chunks, 2 per thread
    const int ar = tid >> 2, ak = (tid & 3) * 8;
    const __half* gA0 = &g_mh[(size_t)(brow + ar) * NN + koff + ak];
    const unsigned sA0 = sb + (unsigned)(ar * APAD + ak) * 2;
    const __half* gA1 = gA0 + (size_t)64 * NN;
    const unsigned sA1 = sA0 + 64 * APAD * 2;

    // B staging: 32 k-rows x 16 chunks of 16B = 512 chunks, 2 per thread
    const int br0 = tid >> 4, bn = (tid & 15) * 8;
    const __half* gB0 = &g_msg[(size_t)(koff + br0) * FDIM + bn];
    const unsigned sB0 = sbB + (unsigned)(br0 * BPAD + bn) * 2;
    const __half* gB1 = gB0 + 16 * FDIM;
    const unsigned sB1 = sB0 + 16 * BPAD * 2;

    // ldmatrix lane addressing
    const int lr  = lane & 15;
    const int lc8 = (lane >> 4) * 8;
    const unsigned aBase = sb + (unsigned)((wm + lr) * APAD + lc8) * 2;
    const unsigned bBase = sbB + (unsigned)(lr * BPAD + wn + lc8) * 2;

    float acc[2][8][4];
#pragma unroll
    for (int mt = 0; mt < 2; mt++)
#pragma unroll
        for (int nt = 0; nt < 8; nt++)
#pragma unroll
            for (int e = 0; e < 4; e++) acc[mt][nt][e] = 0.f;

    // prefetch NSTAGE-1 tiles
#pragma unroll
    for (int s = 0; s < NSTAGE - 1; s++) {
        cp_async16(sA0 + s * ABYTES, gA0 + s * BK);
        cp_async16(sA1 + s * ABYTES, gA1 + s * BK);
        cp_async16(sB0 + s * BBYTES, gB0 + (size_t)s * BK * FDIM);
        cp_async16(sB1 + s * BBYTES, gB1 + (size_t)s * BK * FDIM);
        cp_commit();
    }

#pragma unroll 1
    for (int kt = 0; kt < KTILES; kt++) {
        cp_wait<NSTAGE - 2>();
        __syncthreads();

        const int t = kt + NSTAGE - 1;
        if (t < KTILES) {
            const int s = t % NSTAGE;
            cp_async16(sA0 + s * ABYTES, gA0 + t * BK);
            cp_async16(sA1 + s * ABYTES, gA1 + t * BK);
            cp_async16(sB0 + s * BBYTES, gB0 + (size_t)t * BK * FDIM);
            cp_async16(sB1 + s * BBYTES, gB1 + (size_t)t * BK * FDIM);
        }
        cp_commit();

        const int st = kt % NSTAGE;
        const unsigned aS = aBase + st * ABYTES;
        const unsigned bS = bBase + st * BBYTES;
#pragma unroll
        for (int kk = 0; kk < BK; kk += 16) {
            unsigned a[2][4], b[4][4];
            ldsm4(a[0], aS + kk * 2);
            ldsm4(a[1], aS + 16 * APAD * 2 + kk * 2);
#pragma unroll
            for (int g = 0; g < 4; g++)
                ldsm4t(b[g], bS + kk * BPAD * 2 + g * 32);
#pragma unroll
            for (int mt = 0; mt < 2; mt++)
#pragma unroll
                for (int nt = 0; nt < 8; nt++)
                    mma_f16(acc[mt][nt], a[mt],
                            b[nt >> 1][(nt & 1) * 2], b[nt >> 1][(nt & 1) * 2 + 1]);
        }
    }

    // epilogue: scale by rsqrt(row_deg), store fp32 partial
#pragma unroll
    for (int mt = 0; mt < 2; mt++) {
        const int row = brow + wm + mt * 16 + (lane >> 2);
        const float rs0 = rsqrtf(g_rowdeg[row]);
        const float rs1 = rsqrtf(g_rowdeg[row + 8]);
#pragma unroll
        for (int nt = 0; nt < 8; nt++) {
            const int col = wn + nt * 8 + (lane & 3) * 2;
            const size_t o0 = (size_t)row * FDIM + col;
            out[o0]                = acc[mt][nt][0] * rs0;
            out[o0 + 1]            = acc[mt][nt][1] * rs0;
            out[o0 + 8 * FDIM]     = acc[mt][nt][2] * rs1;
            out[o0 + 8 * FDIM + 1] = acc[mt][nt][3] * rs1;
        }
    }
}

// ---------------------------------------------------------------------------
// Pool stage 1: grid (64, 8). Block = 16 rows of one graph; thread = column.
// Values are >= 0, so atomicMax on raw float bits is order-correct and a
// zero-initialized accumulator is a valid identity.
__global__ __launch_bounds__(FDIM) void pool_max_kernel() {
    const int gidx = blockIdx.x;
    const int seg  = blockIdx.y;
    const int c    = threadIdx.x;
    const size_t base = ((size_t)gidx * 128 + seg * 16) * FDIM + c;
    float mx = 0.f;
#pragma unroll
    for (int r = 0; r < 16; r++) {
        const size_t o = base + (size_t)r * FDIM;
        mx = fmaxf(mx, (g_h0[o] + g_h1[o]) + (g_h2[o] + g_h3[o]));
    }
    atomicMax(&g_poolbits[gidx * FDIM + c], __float_as_uint(mx));
}

// Pool stage 2: logits = pooled @ wc^T + bc. Grid 64 x 128 threads.
__global__ __launch_bounds__(FDIM) void classify_kernel(
    const float* __restrict__ wc, const float* __restrict__ bc,
    float* __restrict__ out) {
    __shared__ float pooled[FDIM];
    const int gidx = blockIdx.x;
    const int c    = threadIdx.x;
    pooled[c] = __uint_as_float(g_poolbits[gidx * FDIM + c]);
    __syncthreads();
    if (c < NCLS) {
        float a = bc[c];
#pragma unroll 8
        for (int k = 0; k < FDIM; k++)
            a += pooled[k] * wc[c * FDIM + k];
        out[gidx * NCLS + c] = a;
    }
}

// ---------------------------------------------------------------------------
extern "C" void kernel_launch(void* const* d_in, const int* in_sizes, int n_in,
                              void* d_out, int out_size) {
    const int*   x   = (const int*)d_in[0];
    const float* m   = (const float*)d_in[1];
    // d_in[2] = bm (unused: segments are exactly contiguous 128-row blocks)
    const float* emb = (const float*)d_in[3];
    const float* w1  = (const float*)d_in[4];
    const float* b1  = (const float*)d_in[5];
    const float* w2  = (const float*)d_in[6];
    const float* b2  = (const float*)d_in[7];
    const float* wc  = (const float*)d_in[8];
    const float* bc  = (const float*)d_in[9];
    float* out = (float*)d_out;

    cudaFuncSetAttribute(gemm_fp16_kernel,
                         cudaFuncAttributeMaxDynamicSharedMemorySize, SMEM_GEMM);
    cudaFuncSetAttribute(linear_kernel,
                         cudaFuncAttributeMaxDynamicSharedMemorySize, SMEM_LIN);

    zero_deg_kernel<<<32, 256>>>();
    degconv_kernel<<<dim3(8, 128), 256>>>(m);

    // layer 1
    linear_kernel<<<NN / 32, 256, SMEM_LIN>>>(emb, x, w1, b1, 1);
    gemm_fp16_kernel<<<dim3(NN / BM, KSPLIT), 256, SMEM_GEMM>>>();
    // layer 2
    linear_kernel<<<NN / 32, 256, SMEM_LIN>>>(nullptr, nullptr, w2, b2, 0);
    gemm_fp16_kernel<<<dim3(NN / BM, KSPLIT), 256, SMEM_GEMM>>>();

    pool_max_kernel<<<dim3(NGRAPH, 8), FDIM>>>();
    classify_kernel<<<NGRAPH, FDIM>>>(wc, bc, out);
}

// round 14
// speedup vs baseline: 1.0358x; 1.0358x over previous
#include <cuda_runtime.h>
#include <cuda_fp16.h>

// ---------------------------------------------------------------------------
// Net_16673063043559: 2-layer dense GCN on GB300 (sm_103a, baseline-PTX only)
//   degconv: row/col sums of m + fp16 conversion (one streaming pass over m)
//   L1:  msg = relu(emb[x] @ w1^T + b1)*csc ; h = rs*(m @ msg)  [split-K=4]
//   L2:  msg = relu((sum g_h0..3) @ w2^T + b2)*csc ; h = rs*(m @ msg)
//   pool: 2-stage segment max (atomicMax on float bits; h >= 0), classify
// Propagate GEMM: fp16 HMMA m16n8k16, CTA tile 128x128, warp tile 32x64,
// cp.async 3-stage ring. (At the legacy mma.sync rate ceiling.)
// Linear: R11 chunked staging (16.9KB smem) + consecutive-column lanes
// (float4 weight LDS, packed uint2 stores). ht indexing is CHUNK-LOCAL (k).
// ---------------------------------------------------------------------------

#define NN     8192
#define FDIM   128
#define NGRAPH 64
#define NCLS   16

// GEMM tiling
#define BM     128
#define BK     32
#define APAD   40     // halves per A smem row (80B stride)
#define BPAD   136    // halves per B smem row (272B stride)
#define NSTAGE 3
#define KSPLIT 4
#define KQ     (NN / KSPLIT)      // 2048
#define KTILES (KQ / BK)          // 64

#define ABYTES (BM * APAD * 2)    // 10240
#define BBYTES (BK * BPAD * 2)    // 8704
#define SMEM_GEMM (NSTAGE * (ABYTES + BBYTES))   // 56832

// Scratch (device globals: no allocation allowed)
__device__ __half g_mh[(size_t)NN * NN];   // fp16 copy of m (128 MB)
__device__ __half g_msg[NN * FDIM];        // scaled message (fp16, GEMM B)
__device__ float  g_h0[NN * FDIM];         // split-K partials (rs-scaled)
__device__ float  g_h1[NN * FDIM];
__device__ float  g_h2[NN * FDIM];
__device__ float  g_h3[NN * FDIM];
__device__ float  g_rowdeg[NN];
__device__ float  g_coldeg[NN];
__device__ unsigned g_poolbits[NGRAPH * FDIM];   // float bits (values >= 0)

// ---------------------------------------------------------------------------
__device__ __forceinline__ unsigned smem_u32(const void* p) {
    return (unsigned)__cvta_generic_to_shared(p);
}
__device__ __forceinline__ void cp_async16(unsigned s, const void* g) {
    asm volatile("cp.async.cg.shared.global [%0], [%1], 16;\n" :: "r"(s), "l"(g));
}
__device__ __forceinline__ void cp_commit() {
    asm volatile("cp.async.commit_group;\n");
}
template <int N>
__device__ __forceinline__ void cp_wait() {
    asm volatile("cp.async.wait_group %0;\n" :: "n"(N));
}
__device__ __forceinline__ void ldsm4(unsigned r[4], unsigned a) {
    asm volatile("ldmatrix.sync.aligned.m8n8.x4.shared.b16 {%0,%1,%2,%3}, [%4];"
                 : "=r"(r[0]), "=r"(r[1]), "=r"(r[2]), "=r"(r[3]) : "r"(a));
}
__device__ __forceinline__ void ldsm4t(unsigned r[4], unsigned a) {
    asm volatile("ldmatrix.sync.aligned.m8n8.x4.trans.shared.b16 {%0,%1,%2,%3}, [%4];"
                 : "=r"(r[0]), "=r"(r[1]), "=r"(r[2]), "=r"(r[3]) : "r"(a));
}
__device__ __forceinline__ void mma_f16(float c[4], const unsigned a[4],
                                        unsigned b0, unsigned b1) {
    asm volatile(
        "mma.sync.aligned.m16n8k16.row.col.f32.f16.f16.f32 "
        "{%0,%1,%2,%3}, {%4,%5,%6,%7}, {%8,%9}, {%0,%1,%2,%3};"
        : "+f"(c[0]), "+f"(c[1]), "+f"(c[2]), "+f"(c[3])
        : "r"(a[0]), "r"(a[1]), "r"(a[2]), "r"(a[3]), "r"(b0), "r"(b1));
}

// ---------------------------------------------------------------------------
// Zero accumulators each replay (atomics accumulate; graph determinism).
__global__ void zero_deg_kernel() {
    int i = blockIdx.x * blockDim.x + threadIdx.x;
    if (i < NN) { g_rowdeg[i] = 0.f; g_coldeg[i] = 0.f; }
    if (i < NGRAPH * FDIM) g_poolbits[i] = 0u;   // valid: pooled values >= 0
}

// ---------------------------------------------------------------------------
// One streaming pass over m: row sums, col sums, fp16 conversion.
// Thread owns 4 consecutive columns. Grid (8, 64) -> 512 CTAs.
__global__ __launch_bounds__(256) void degconv_kernel(const float* __restrict__ m) {
    const int c    = (blockIdx.x * 256 + threadIdx.x) * 4;
    const int r0   = blockIdx.y * 128;
    const int lane = threadIdx.x & 31;
    float ca0 = 0.f, ca1 = 0.f, ca2 = 0.f, ca3 = 0.f;

    for (int r = r0; r < r0 + 128; r += 8) {
        float4 v[8];
        float  rs[8];
#pragma unroll
        for (int j = 0; j < 8; j++)
            v[j] = __ldcs((const float4*)&m[(size_t)(r + j) * NN + c]);
#pragma unroll
        for (int j = 0; j < 8; j++) {
            __half2 h01 = __floats2half2_rn(v[j].x, v[j].y);
            __half2 h23 = __floats2half2_rn(v[j].z, v[j].w);
            uint2 pk = make_uint2(*(unsigned*)&h01, *(unsigned*)&h23);
            __stcs((uint2*)&g_mh[(size_t)(r + j) * NN + c], pk);
            ca0 += v[j].x; ca1 += v[j].y; ca2 += v[j].z; ca3 += v[j].w;
            rs[j] = (v[j].x + v[j].y) + (v[j].z + v[j].w);
        }
#pragma unroll
        for (int j = 0; j < 8; j++) {
            rs[j] += __shfl_xor_sync(0xffffffffu, rs[j], 16);
            rs[j] += __shfl_xor_sync(0xffffffffu, rs[j], 8);
            rs[j] += __shfl_xor_sync(0xffffffffu, rs[j], 4);
            rs[j] += __shfl_xor_sync(0xffffffffu, rs[j], 2);
            rs[j] += __shfl_xor_sync(0xffffffffu, rs[j], 1);
        }
        if (lane == 0) {
#pragma unroll
            for (int j = 0; j < 8; j++)
                atomicAdd(&g_rowdeg[r + j], rs[j]);
        }
    }
    atomicAdd(&g_coldeg[c + 0], ca0);
    atomicAdd(&g_coldeg[c + 1], ca1);
    atomicAdd(&g_coldeg[c + 2], ca2);
    atomicAdd(&g_coldeg[c + 3], ca3);
}

// ---------------------------------------------------------------------------
// g_msg = relu(in @ w^T + b) * rsqrt(col_deg[row]) as fp16.
// in = gather(emb, x) (gather=1) or g_h0+g_h1+g_h2+g_h3 (gather=0).
// Chunked staging; ht holds the CURRENT 32-k chunk at local offsets 0..31.
// Lane owns 4 consecutive cols -> one float4 weight LDS per k, packed stores.
__global__ __launch_bounds__(256) void linear_kernel(
    const float* __restrict__ ext, const int* __restrict__ idx,
    const float* __restrict__ w, const float* __restrict__ b, int gather) {
    __shared__ float ht[32 * 36];
    __shared__ float wt[32 * 132];

    const int tid  = threadIdx.x;
    const int brow = blockIdx.x * 32;
    const int rg   = tid >> 5;          // warp -> 4 nodes
    const int cg   = tid & 31;          // lane -> cols [4cg, 4cg+4)

    const int sr   = tid >> 3;
    const int sk4  = (tid & 7) << 2;
    const int node = brow + sr;
    const float* src = gather ? (ext + (size_t)idx[node] * FDIM)
                              : (const float*)&g_h0[(size_t)node * FDIM];

    float acc[4][4];
#pragma unroll
    for (int j = 0; j < 4; j++)
#pragma unroll
        for (int jj = 0; jj < 4; jj++) acc[j][jj] = 0.f;

    for (int kc = 0; kc < 4; kc++) {
        const int k0 = kc * 32;
        if (kc) __syncthreads();

        float4 hv = *(const float4*)(src + k0 + sk4);
        if (!gather) {
            const size_t o = (size_t)node * FDIM + k0 + sk4;
            float4 h1 = *(const float4*)&g_h1[o];
            float4 h2 = *(const float4*)&g_h2[o];
            float4 h3 = *(const float4*)&g_h3[o];
            hv.x += h1.x + h2.x + h3.x;
            hv.y += h1.y + h2.y + h3.y;
            hv.z += h1.z + h2.z + h3.z;
            hv.w += h1.w + h2.w + h3.w;
        }
        ht[sr * 36 + sk4 + 0] = hv.x;
        ht[sr * 36 + sk4 + 1] = hv.y;
        ht[sr * 36 + sk4 + 2] = hv.z;
        ht[sr * 36 + sk4 + 3] = hv.w;

#pragma unroll
        for (int i = 0; i < 4; i++) {
            int lin4 = tid + i * 256;
            int c    = lin4 >> 3;
            int kk4  = (lin4 & 7) << 2;
            float4 wv = *(const float4*)(w + (size_t)c * FDIM + k0 + kk4);
            wt[(kk4 + 0) * 132 + c] = wv.x;
            wt[(kk4 + 1) * 132 + c] = wv.y;
            wt[(kk4 + 2) * 132 + c] = wv.z;
            wt[(kk4 + 3) * 132 + c] = wv.w;
        }
        __syncthreads();

#pragma unroll
        for (int k = 0; k < 32; k++) {
            float4 wv = *(const float4*)&wt[k * 132 + cg * 4];
            float hvv[4];
#pragma unroll
            for (int j = 0; j < 4; j++) hvv[j] = ht[(rg * 4 + j) * 36 + k];  // chunk-local
#pragma unroll
            for (int j = 0; j < 4; j++) {
                acc[j][0] += hvv[j] * wv.x;
                acc[j][1] += hvv[j] * wv.y;
                acc[j][2] += hvv[j] * wv.z;
                acc[j][3] += hvv[j] * wv.w;
            }
        }
    }

    const float4 bv = *(const float4*)&b[cg * 4];
#pragma unroll
    for (int j = 0; j < 4; j++) {
        const int rr = brow + rg * 4 + j;
        const float sc = rsqrtf(g_coldeg[rr]);
        float v0 = fmaxf(acc[j][0] + bv.x, 0.f) * sc;
        float v1 = fmaxf(acc[j][1] + bv.y, 0.f) * sc;
        float v2 = fmaxf(acc[j][2] + bv.z, 0.f) * sc;
        float v3 = fmaxf(acc[j][3] + bv.w, 0.f) * sc;
        __half2 h01 = __floats2half2_rn(v0, v1);
        __half2 h23 = __floats2half2_rn(v2, v3);
        *(uint2*)&g_msg[(size_t)rr * FDIM + cg * 4] =
            make_uint2(*(unsigned*)&h01, *(unsigned*)&h23);
    }
}

// ---------------------------------------------------------------------------
// Split-K propagate GEMM: partial = rs * (g_mh[:, Ks] @ g_msg[Ks, :]).
// Grid (64, 4): x = M tile (128 rows), y = K quarter. 256 CTAs, 2/SM.
// 8 warps: 4 along m (32 rows each) x 2 along n (64 cols each).
__global__ void __launch_bounds__(256, 2) gemm_fp16_kernel() {
    extern __shared__ __half smem[];
    const unsigned sb  = smem_u32(smem);              // A stages base
    const unsigned sbB = sb + NSTAGE * ABYTES;        // B stages base

    const int tid  = threadIdx.x;
    const int brow = blockIdx.x * BM;
    const int koff = blockIdx.y * KQ;
    float* out = (blockIdx.y == 0) ? g_h0 :
                 (blockIdx.y == 1) ? g_h1 :
                 (blockIdx.y == 2) ? g_h2 : g_h3;

    const int warp = tid >> 5, lane = tid & 31;
    const int wm   = (warp & 3) * 32;     // 0,32,64,96
    const int wn   = (warp >> 2) * 64;    // 0,64

    // A staging: 128 rows x 4 chunks of 16B = 512 chunks, 2 per thread
    const int ar = tid >> 2, ak = (tid & 3) * 8;
    const __half* gA0 = &g_mh[(size_t)(brow + ar) * NN + koff + ak];
    const unsigned sA0 = sb + (unsigned)(ar * APAD + ak) * 2;
    const __half* gA1 = gA0 + (size_t)64 * NN;
    const unsigned sA1 = sA0 + 64 * APAD * 2;

    // B staging: 32 k-rows x 16 chunks of 16B = 512 chunks, 2 per thread
    const int br0 = tid >> 4, bn = (tid & 15) * 8;
    const __half* gB0 = &g_msg[(size_t)(koff + br0) * FDIM + bn];
    const unsigned sB0 = sbB + (unsigned)(br0 * BPAD + bn) * 2;
    const __half* gB1 = gB0 + 16 * FDIM;
    const unsigned sB1 = sB0 + 16 * BPAD * 2;

    // ldmatrix lane addressing
    const int lr  = lane & 15;
    const int lc8 = (lane >> 4) * 8;
    const unsigned aBase = sb + (unsigned)((wm + lr) * APAD + lc8) * 2;
    const unsigned bBase = sbB + (unsigned)(lr * BPAD + wn + lc8) * 2;

    float acc[2][8][4];
#pragma unroll
    for (int mt = 0; mt < 2; mt++)
#pragma unroll
        for (int nt = 0; nt < 8; nt++)
#pragma unroll
            for (int e = 0; e < 4; e++) acc[mt][nt][e] = 0.f;

    // prefetch NSTAGE-1 tiles
#pragma unroll
    for (int s = 0; s < NSTAGE - 1; s++) {
        cp_async16(sA0 + s * ABYTES, gA0 + s * BK);
        cp_async16(sA1 + s * ABYTES, gA1 + s * BK);
        cp_async16(sB0 + s * BBYTES, gB0 + (size_t)s * BK * FDIM);
        cp_async16(sB1 + s * BBYTES, gB1 + (size_t)s * BK * FDIM);
        cp_commit();
    }

#pragma unroll 1
    for (int kt = 0; kt < KTILES; kt++) {
        cp_wait<NSTAGE - 2>();
        __syncthreads();

        const int t = kt + NSTAGE - 1;
        if (t < KTILES) {
            const int s = t % NSTAGE;
            cp_async16(sA0 + s * ABYTES, gA0 + t * BK);
            cp_async16(sA1 + s * ABYTES, gA1 + t * BK);
            cp_async16(sB0 + s * BBYTES, gB0 + (size_t)t * BK * FDIM);
            cp_async16(sB1 + s * BBYTES, gB1 + (size_t)t * BK * FDIM);
        }
        cp_commit();

        const int st = kt % NSTAGE;
        const unsigned aS = aBase + st * ABYTES;
        const unsigned bS = bBase + st * BBYTES;
#pragma unroll
        for (int kk = 0; kk < BK; kk += 16) {
            unsigned a[2][4], b[4][4];
            ldsm4(a[0], aS + kk * 2);
            ldsm4(a[1], aS + 16 * APAD * 2 + kk * 2);
#pragma unroll
            for (int g = 0; g < 4; g++)
                ldsm4t(b[g], bS + kk * BPAD * 2 + g * 32);
#pragma unroll
            for (int mt = 0; mt < 2; mt++)
#pragma unroll
                for (int nt = 0; nt < 8; nt++)
                    mma_f16(acc[mt][nt], a[mt],
                            b[nt >> 1][(nt & 1) * 2], b[nt >> 1][(nt & 1) * 2 + 1]);
        }
    }

    // epilogue: scale by rsqrt(row_deg), store fp32 partial
#pragma unroll
    for (int mt = 0; mt < 2; mt++) {
        const int row = brow + wm + mt * 16 + (lane >> 2);
        const float rs0 = rsqrtf(g_rowdeg[row]);
        const float rs1 = rsqrtf(g_rowdeg[row + 8]);
#pragma unroll
        for (int nt = 0; nt < 8; nt++) {
            const int col = wn + nt * 8 + (lane & 3) * 2;
            const size_t o0 = (size_t)row * FDIM + col;
            out[o0]                = acc[mt][nt][0] * rs0;
            out[o0 + 1]            = acc[mt][nt][1] * rs0;
            out[o0 + 8 * FDIM]     = acc[mt][nt][2] * rs1;
            out[o0 + 8 * FDIM + 1] = acc[mt][nt][3] * rs1;
        }
    }
}

// ---------------------------------------------------------------------------
// Pool stage 1: grid (64, 8). Block = 16 rows of one graph; thread = column.
// Values are >= 0, so atomicMax on raw float bits is order-correct and a
// zero-initialized accumulator is a valid identity.
__global__ __launch_bounds__(FDIM) void pool_max_kernel() {
    const int gidx = blockIdx.x;
    const int seg  = blockIdx.y;
    const int c    = threadIdx.x;
    const size_t base = ((size_t)gidx * 128 + seg * 16) * FDIM + c;
    float mx = 0.f;
#pragma unroll
    for (int r = 0; r < 16; r++) {
        const size_t o = base + (size_t)r * FDIM;
        mx = fmaxf(mx, (g_h0[o] + g_h1[o]) + (g_h2[o] + g_h3[o]));
    }
    atomicMax(&g_poolbits[gidx * FDIM + c], __float_as_uint(mx));
}

// Pool stage 2: logits = pooled @ wc^T + bc. Grid 64 x 128 threads.
__global__ __launch_bounds__(FDIM) void classify_kernel(
    const float* __restrict__ wc, const float* __restrict__ bc,
    float* __restrict__ out) {
    __shared__ float pooled[FDIM];
    const int gidx = blockIdx.x;
    const int c    = threadIdx.x;
    pooled[c] = __uint_as_float(g_poolbits[gidx * FDIM + c]);
    __syncthreads();
    if (c < NCLS) {
        float a = bc[c];
#pragma unroll 8
        for (int k = 0; k < FDIM; k++)
            a += pooled[k] * wc[c * FDIM + k];
        out[gidx * NCLS + c] = a;
    }
}

// ---------------------------------------------------------------------------
extern "C" void kernel_launch(void* const* d_in, const int* in_sizes, int n_in,
                              void* d_out, int out_size) {
    const int*   x   = (const int*)d_in[0];
    const float* m   = (const float*)d_in[1];
    // d_in[2] = bm (unused: segments are exactly contiguous 128-row blocks)
    const float* emb = (const float*)d_in[3];
    const float* w1  = (const float*)d_in[4];
    const float* b1  = (const float*)d_in[5];
    const float* w2  = (const float*)d_in[6];
    const float* b2  = (const float*)d_in[7];
    const float* wc  = (const float*)d_in[8];
    const float* bc  = (const float*)d_in[9];
    float* out = (float*)d_out;

    cudaFuncSetAttribute(gemm_fp16_kernel,
                         cudaFuncAttributeMaxDynamicSharedMemorySize, SMEM_GEMM);

    zero_deg_kernel<<<32, 256>>>();
    degconv_kernel<<<dim3(8, 64), 256>>>(m);

    // layer 1
    linear_kernel<<<NN / 32, 256>>>(emb, x, w1, b1, 1);
    gemm_fp16_kernel<<<dim3(NN / BM, KSPLIT), 256, SMEM_GEMM>>>();
    // layer 2
    linear_kernel<<<NN / 32, 256>>>(nullptr, nullptr, w2, b2, 0);
    gemm_fp16_kernel<<<dim3(NN / BM, KSPLIT), 256, SMEM_GEMM>>>();

    pool_max_kernel<<<dim3(NGRAPH, 8), FDIM>>>();
    classify_kernel<<<NGRAPH, FDIM>>>(wc, bc, out);
}